// round 1
// baseline (speedup 1.0000x reference)
#include <cuda_runtime.h>
#include <math.h>

#define IN_F   512
#define HID    256
#define BATCH  1024

// Precomputed edge masks: bit set = "normal edge" (take x), clear = no_edge.
__device__ unsigned int g_mask0[HID * (IN_F / 32)];  // [256][16]
__device__ unsigned int g_mask1[IN_F * (HID / 32)];  // [512][8]

// ---------------------------------------------------------------------------
// Kernel 1: build bitmasks from (logits, u). One thread per edge, ballot-pack.
// argmax_e softmax(logits+g) == argmax_e (logits+g); tie -> e=0.
// Fast path logits equal: g monotone in clipped u  =>  compare u directly.
// ---------------------------------------------------------------------------
__global__ __launch_bounds__(256)
void mask_kernel(const float* __restrict__ logits0, const float* __restrict__ u0,
                 const float* __restrict__ logits1, const float* __restrict__ u1)
{
    int g = blockIdx.x * blockDim.x + threadIdx.x;   // 0 .. 262143
    const float* L;
    const float* U;
    unsigned int* M;
    int idx;
    if (g < HID * IN_F) { L = logits0; U = u0; M = g_mask0; idx = g; }
    else                { L = logits1; U = u1; M = g_mask1; idx = g - HID * IN_F; }

    float2 l = reinterpret_cast<const float2*>(L)[idx];
    float2 u = reinterpret_cast<const float2*>(U)[idx];

    const float LO = 1e-10f;
    const float HI = 1.0f - 1e-10f;   // == 1.0f in fp32, same as JAX's clip bound
    float ca = fminf(fmaxf(u.x, LO), HI);
    float cb = fminf(fmaxf(u.y, LO), HI);

    bool pred;
    if (l.x == l.y) {
        pred = cb > ca;                       // monotone shortcut
    } else {
        float g0 = -logf(-logf(ca));
        float g1 = -logf(-logf(cb));
        pred = (l.y + g1) > (l.x + g0);
    }

    unsigned bal = __ballot_sync(0xFFFFFFFFu, pred);
    if ((threadIdx.x & 31) == 0) M[idx >> 5] = bal;
}

// ---------------------------------------------------------------------------
// In-shared bitonic sort of N u32 keys, 256 threads (N/2 compare-exchanges
// per phase, threads t >= N/2 idle but hit the barriers).
// ---------------------------------------------------------------------------
template <int N>
__device__ __forceinline__ void bitonic_sort(unsigned int* s, int t)
{
#pragma unroll
    for (int k = 2; k <= N; k <<= 1) {
#pragma unroll
        for (int j = k >> 1; j > 0; j >>= 1) {
            if (t < N / 2) {
                int i = ((t & ~(j - 1)) << 1) | (t & (j - 1));
                int p = i | j;
                bool up = ((i & k) == 0);
                unsigned a = s[i], c = s[p];
                if ((a > c) == up) { s[i] = c; s[p] = a; }
            }
            __syncthreads();
        }
    }
}

// ---------------------------------------------------------------------------
// Kernel 2: fused two-layer evaluation, one block per batch row.
//   1) sort x-row ascending (quantized key | index)
//   2) each thread (one hidden unit) probes sorted order for first masked hit
//      -> exact min via tie-group rescan
//   3) sort h descending, probe for layer-1 max (2 outputs per thread)
// ---------------------------------------------------------------------------
__global__ __launch_bounds__(256)
void row_kernel(const float* __restrict__ x, float* __restrict__ out)
{
    __shared__ unsigned int skey[IN_F];   // sort keys (reused for both layers)
    __shared__ float        sval[IN_F];   // exact x row
    __shared__ float        shv[HID];     // exact h row

    const int b = blockIdx.x;
    const int t = threadIdx.x;            // 0..255

    // ---- load x row, build ascending keys: (xbits>>7)<<9 | idx ----
#pragma unroll
    for (int i = t; i < IN_F; i += 256) {
        float v = x[b * IN_F + i];
        sval[i] = v;
        unsigned bits = __float_as_uint(v);         // v in [0,1): bits <= 0x3F7FFFFF
        skey[i] = ((bits >> 7) << 9) | (unsigned)i;
    }
    __syncthreads();

    bitonic_sort<IN_F>(skey, t);

    // ---- layer 0 probe: thread t owns hidden unit o = t ----
    const unsigned int* m0 = &g_mask0[t * (IN_F / 32)];
    float h = 1.0f;                                  // default: no selected edge
    for (int k = 0; k < IN_F; k++) {
        unsigned key = skey[k];
        unsigned i   = key & 511u;
        unsigned w   = m0[i >> 5];
        if ((w >> (i & 31)) & 1u) {
            h = sval[i];
            unsigned qhi = key >> 9;                 // exact-min rescan of tie group
            for (int k2 = k + 1; k2 < IN_F; k2++) {
                unsigned key2 = skey[k2];
                if ((key2 >> 9) != qhi) break;
                unsigned i2 = key2 & 511u;
                unsigned w2 = m0[i2 >> 5];
                if ((w2 >> (i2 & 31)) & 1u) h = fminf(h, sval[i2]);
            }
            break;
        }
    }
    __syncthreads();                                 // probes done before reuse

    // ---- build descending keys for h (h in [0,1] -> hbits<=0x3F800000) ----
    shv[t] = h;
    unsigned hb = __float_as_uint(h);
    skey[t] = ((0x7FFFFFu - (hb >> 7)) << 9) | (unsigned)t;
    __syncthreads();

    bitonic_sort<HID>(skey, t);

    // ---- layer 1 probe: thread t owns outputs o = t and t + 256 ----
#pragma unroll
    for (int half = 0; half < 2; half++) {
        int o = t + half * 256;
        const unsigned int* m1 = &g_mask1[o * (HID / 32)];
        float r = 0.0f;                              // default: no selected edge
        for (int k = 0; k < HID; k++) {
            unsigned key = skey[k];
            unsigned j   = key & 511u;
            unsigned w   = m1[j >> 5];
            if ((w >> (j & 31)) & 1u) {
                r = shv[j];
                unsigned qhi = key >> 9;             // exact-max rescan of tie group
                for (int k2 = k + 1; k2 < HID; k2++) {
                    unsigned key2 = skey[k2];
                    if ((key2 >> 9) != qhi) break;
                    unsigned j2 = key2 & 511u;
                    unsigned w2 = m1[j2 >> 5];
                    if ((w2 >> (j2 & 31)) & 1u) r = fmaxf(r, shv[j2]);
                }
                break;
            }
        }
        out[b * IN_F + o] = r;
    }
}

// ---------------------------------------------------------------------------
// kernel_launch: graph-capturable, allocation-free.
// Input order (metadata): x, logits0, u0, logits1, u1. Output: float32 [1024,512].
// ---------------------------------------------------------------------------
extern "C" void kernel_launch(void* const* d_in, const int* in_sizes, int n_in,
                              void* d_out, int out_size)
{
    const float* x       = (const float*)d_in[0];
    const float* logits0 = (const float*)d_in[1];
    const float* u0      = (const float*)d_in[2];
    const float* logits1 = (const float*)d_in[3];
    const float* u1      = (const float*)d_in[4];
    float* out = (float*)d_out;

    // 262144 edges total, one thread per edge
    mask_kernel<<<(HID * IN_F * 2) / 256, 256>>>(logits0, u0, logits1, u1);
    // one block per batch row
    row_kernel<<<BATCH, 256>>>(x, out);
}